// round 8
// baseline (speedup 1.0000x reference)
#include <cuda_runtime.h>
#include <cstdint>
#include <utility>

#define HD __host__ __device__

using u64 = unsigned long long;

// ---------------------------------------------------------------------------
// Compile-time Clebsch-Gordan machinery (mirrors the numpy reference exactly)
// ---------------------------------------------------------------------------

HD constexpr double cfac(int n) {
    double r = 1.0;
    for (int i = 2; i <= n; ++i) r *= (double)i;
    return r;
}

HD constexpr double csqrt(double x) {
    if (x <= 0.0) return 0.0;
    double g = x > 1.0 ? x : 1.0;
    for (int i = 0; i < 64; ++i) g = 0.5 * (g + x / g);
    return g;
}

HD constexpr int imax3(int a, int b, int c) { int m = a; if (b > m) m = b; if (c > m) m = c; return m; }
HD constexpr int imin3(int a, int b, int c) { int m = a; if (b < m) m = b; if (c < m) m = c; return m; }
HD constexpr int iabs(int a) { return a < 0 ? -a : a; }
HD constexpr double m1p(int k) { return (k & 1) ? -1.0 : 1.0; }

HD constexpr double wcg(int j1, int m1, int j2, int m2, int j3, int m3) {
    if (m1 + m2 != m3) return 0.0;
    if (j3 < iabs(j1 - j2) || j3 > j1 + j2) return 0.0;
    double pre = csqrt((2 * j3 + 1) * cfac(j3 + j1 - j2) * cfac(j3 - j1 + j2) *
                       cfac(j1 + j2 - j3) / cfac(j1 + j2 + j3 + 1));
    pre = pre * csqrt(cfac(j3 + m3) * cfac(j3 - m3) * cfac(j1 - m1) *
                      cfac(j1 + m1) * cfac(j2 - m2) * cfac(j2 + m2));
    double s = 0.0;
    int k0 = imax3(0, j2 - j3 - m1, j1 - j3 + m2);
    int k1 = imin3(j1 + j2 - j3, j1 - m1, j2 + m2);
    for (int k = k0; k <= k1; ++k) {
        s += m1p(k) / (cfac(k) * cfac(j1 + j2 - j3 - k) * cfac(j1 - m1 - k) *
                       cfac(j2 + m2 - k) * cfac(j3 - j2 + m1 + k) * cfac(j3 - j1 - m2 + k));
    }
    return pre * s;
}

struct C2 { double re, im; };
constexpr double S2C = 0.70710678118654752440;

HD constexpr C2 uent(int l, int a, int A) {
    int m = a - l, M = A - l;
    if (m > 0) {
        if (M == m)  return C2{ m1p(m) * S2C, 0.0 };
        if (M == -m) return C2{ S2C, 0.0 };
    } else if (m == 0) {
        if (M == 0) return C2{ 1.0, 0.0 };
    } else {
        int am = -m;
        if (M == m)  return C2{ 0.0, S2C };
        if (M == am) return C2{ 0.0, -m1p(am) * S2C };
    }
    return C2{ 0.0, 0.0 };
}

HD constexpr double rcg_d(int l1, int l2, int l3, int a, int b, int c) {
    double re = 0.0, im = 0.0;
    for (int A = 0; A < 2 * l1 + 1; ++A) {
        for (int B = 0; B < 2 * l2 + 1; ++B) {
            int m1 = A - l1, m2 = B - l2, m3 = m1 + m2;
            if (m3 < -l3 || m3 > l3) continue;
            double cgv = wcg(l1, m1, l2, m2, l3, m3);
            if (cgv == 0.0) continue;
            C2 u1 = uent(l1, a, A);
            if (u1.re == 0.0 && u1.im == 0.0) continue;
            C2 u2 = uent(l2, b, B);
            if (u2.re == 0.0 && u2.im == 0.0) continue;
            C2 u3 = uent(l3, c, m3 + l3);
            double pr = u1.re * u2.re - u1.im * u2.im;
            double pi = u1.re * u2.im + u1.im * u2.re;
            re += (pr * u3.re + pi * u3.im) * cgv;
            im += (pi * u3.re - pr * u3.im) * cgv;
        }
    }
    return ((l1 + l2 + l3) & 1) ? im : re;
}

HD constexpr float rcg_f(int l1, int l2, int l3, int a, int b, int c) {
    double v = rcg_d(l1, l2, l3, a, b, c);
    return (v > 1e-8 || v < -1e-8) ? (float)v : 0.0f;
}

// nnz across the c-row for (a,b)
HD constexpr int nnz_ab(int l1, int l2, int l3, int a, int b) {
    int k = 0;
    for (int c = 0; c < 2 * l3 + 1; ++c)
        if (rcg_f(l1, l2, l3, a, b, c) != 0.0f) ++k;
    return k;
}
// true if the row's single nonzero equals exactly 1.0f
HD constexpr bool identity_ab(int l1, int l2, int l3, int a, int b) {
    if (nnz_ab(l1, l2, l3, a, b) != 1) return false;
    for (int c = 0; c < 2 * l3 + 1; ++c) {
        float g = rcg_f(l1, l2, l3, a, b, c);
        if (g != 0.0f) return g == 1.0f;
    }
    return false;
}

// ---------------------------------------------------------------------------
// constexpr IEEE754 encode: float -> bits; duplicate into 64-bit (g,g) pair
// ---------------------------------------------------------------------------
HD constexpr unsigned f2b(float x) {
    if (x == 0.0f) return 0u;
    unsigned s = 0; double v = x;
    if (v < 0.0) { s = 0x80000000u; v = -v; }
    int e = 0;
    while (v >= 2.0) { v *= 0.5; ++e; }
    while (v < 1.0)  { v *= 2.0; --e; }
    double mf = (v - 1.0) * 8388608.0;
    unsigned mant = (unsigned)(mf + 0.5);
    if (mant == 8388608u) { mant = 0; ++e; }
    return s | ((unsigned)(e + 127) << 23) | mant;
}
HD constexpr u64 dup2(float x) {
    unsigned b = f2b(x);
    return ((u64)b << 32) | (u64)b;
}

// ---------------------------------------------------------------------------
// Path table
// ---------------------------------------------------------------------------
constexpr int NPATH = 33;
HD constexpr int PL1f(int p) {
    constexpr int t[NPATH] = {0,0,0,0,0, 1,1,1,1,1,1,1,1,1,1,1,1, 2,2,2,2,2,2,2,2,2,2,2,2,2,2,2,2};
    return t[p];
}
HD constexpr int PL2f(int p) {
    constexpr int t[NPATH] = {0,1,2,3,4, 0,1,1,1,2,2,2,3,3,3,4,4, 0,1,1,1,2,2,2,2,2,3,3,3,3,4,4,4};
    return t[p];
}
HD constexpr int PL3f(int p) {
    constexpr int t[NPATH] = {0,1,2,3,4, 1,0,1,2,1,2,3,2,3,4,3,4, 2,1,2,3,0,1,2,3,4,1,2,3,4,2,3,4};
    return t[p];
}

// ---------------------------------------------------------------------------
// static_for
// ---------------------------------------------------------------------------
template <class F, int... Is>
__device__ __forceinline__ void sf_impl(F&& f, std::integer_sequence<int, Is...>) {
    (f(std::integral_constant<int, Is>{}), ...);
}
template <int N, class F>
__device__ __forceinline__ void static_for(F&& f) {
    sf_impl(static_cast<F&&>(f), std::make_integer_sequence<int, N>{});
}

// ---------------------------------------------------------------------------
// packed f32x2 primitives
// ---------------------------------------------------------------------------
__device__ __forceinline__ u64 pk2(float lo, float hi) {
    u64 r; asm("mov.b64 %0, {%1, %2};" : "=l"(r) : "f"(lo), "f"(hi)); return r;
}
__device__ __forceinline__ u64 fma2(u64 a, u64 b, u64 c) {
    u64 d; asm("fma.rn.f32x2 %0, %1, %2, %3;" : "=l"(d) : "l"(a), "l"(b), "l"(c)); return d;
}
__device__ __forceinline__ u64 mul2(u64 a, u64 b) {
    u64 d; asm("mul.rn.f32x2 %0, %1, %2;" : "=l"(d) : "l"(a), "l"(b)); return d;
}
__device__ __forceinline__ u64 add2(u64 a, u64 b) {
    u64 d; asm("add.rn.f32x2 %0, %1, %2;" : "=l"(d) : "l"(a), "l"(b)); return d;
}

// ---------------------------------------------------------------------------
// Kernel: one thread handles one edge x one feature PAIR (f=2fp, 2fp+1)
// ---------------------------------------------------------------------------

template <int L3, int P>
__device__ __forceinline__ void do_path(u64 (&acc)[2][2 * L3 + 1],
                                        const u64 (&yv)[25], const float (&sh)[9],
                                        u64 rad2, const float* __restrict__ w, int f2) {
    constexpr int l1 = PL1f(P);
    constexpr int l2 = PL2f(P);
    constexpr int par = (l1 + l2 + L3) & 1;
    // packed weights for both features of this thread, times radial
    u64 w2 = __ldg(reinterpret_cast<const u64*>(w + P * 16 + f2));
    u64 wr = mul2(w2, rad2);
    static_for<2 * l1 + 1>([&](auto IA) {
        constexpr int a = decltype(IA)::value;
        float shs = sh[l1 * l1 + a];
        u64 pa = mul2(wr, pk2(shs, shs));
        static_for<2 * l2 + 1>([&](auto IB) {
            constexpr int b = decltype(IB)::value;
            constexpr int nnz = nnz_ab(l1, l2, L3, a, b);
            if constexpr (nnz == 1 && identity_ab(l1, l2, L3, a, b)) {
                // G entry is exactly 1 (identity paths): fuse, no prod mul
                static_for<2 * L3 + 1>([&](auto IC) {
                    constexpr int c = decltype(IC)::value;
                    constexpr float g = rcg_f(l1, l2, L3, a, b, c);
                    if constexpr (g != 0.0f) {
                        acc[par][c] = fma2(pa, yv[l2 * l2 + b], acc[par][c]);
                    }
                });
            } else if constexpr (nnz > 0) {
                u64 prod = mul2(pa, yv[l2 * l2 + b]);
                static_for<2 * L3 + 1>([&](auto IC) {
                    constexpr int c = decltype(IC)::value;
                    constexpr float g = rcg_f(l1, l2, L3, a, b, c);
                    if constexpr (g != 0.0f) {
                        constexpr u64 GG = dup2(g);
                        acc[par][c] = fma2(GG, prod, acc[par][c]);
                    }
                });
            }
        });
    });
}

template <int L3>
__device__ __forceinline__ void do_l3(const u64 (&yv)[25], const float (&sh)[9],
                                      u64 rad2, const float* __restrict__ w, int f2,
                                      float* __restrict__ ob) {
    u64 acc[2][2 * L3 + 1];
#pragma unroll
    for (int p = 0; p < 2; ++p)
#pragma unroll
        for (int c = 0; c < 2 * L3 + 1; ++c) acc[p][c] = 0ull;

    static_for<NPATH>([&](auto IP) {
        constexpr int P = decltype(IP)::value;
        if constexpr (PL3f(P) == L3) {
            do_path<L3, P>(acc, yv, sh, rad2, w, f2);
        }
    });

#pragma unroll
    for (int par = 0; par < 2; ++par)
#pragma unroll
        for (int c = 0; c < 2 * L3 + 1; ++c)
            *reinterpret_cast<u64*>(ob + (par * 25 + L3 * L3 + c) * 16) = acc[par][c];
}

__global__ __launch_bounds__(128, 6)
void bctm_kernel(const float* __restrict__ desc,   // (N_ATOMS, 1, 25, 16)
                 const float* __restrict__ w,      // (33, 16)
                 const float* __restrict__ disp,   // (E, 3)
                 const int* __restrict__ idx,      // (E, 2)
                 float* __restrict__ out,          // (E, 2, 25, 16)
                 int E) {
    int t = blockIdx.x * blockDim.x + threadIdx.x;
    int e = t >> 3;
    int fp = t & 7;          // feature pair index: features 2fp, 2fp+1
    int f2 = fp * 2;
    if (e >= E) return;

    int i0 = __ldg(idx + 2 * e);
    int i1 = __ldg(idx + 2 * e + 1);
    float dx = __ldg(disp + 3 * e);
    float dy = __ldg(disp + 3 * e + 1);
    float dz = __ldg(disp + 3 * e + 2);

    float r = sqrtf(dx * dx + dy * dy + dz * dz);
    float inv = 1.0f / fmaxf(r, 1e-9f);
    float ux = dx * inv, uy = dy * inv, uz = dz * inv;

    // spherical harmonics, scalar (identical for both packed feature lanes)
    float sh[9];
    {
        const float c1 = 0.4886025119029199f;
        const float c2 = 1.0925484305920792f;
        sh[0] = 0.28209479177387814f;
        sh[1] = c1 * uy;
        sh[2] = c1 * uz;
        sh[3] = c1 * ux;
        sh[4] = c2 * ux * uy;
        sh[5] = c2 * uy * uz;
        sh[6] = 0.31539156525252005f * (3.0f * uz * uz - 1.0f);
        sh[7] = c2 * ux * uz;
        sh[8] = 0.5f * c2 * (ux * ux - uy * uy);
    }

    // radial sinc for the two features of this thread
    float rlo = 0.0f, rhi = 0.0f;
    if (r < 5.0f) {
        float pxl = 0.6283185307179586f * (float)(f2 + 1) * r;
        float pxh = 0.6283185307179586f * (float)(f2 + 2) * r;
        rlo = (pxl < 1e-6f) ? 1.0f : __fdividef(__sinf(pxl), pxl);
        rhi = (pxh < 1e-6f) ? 1.0f : __fdividef(__sinf(pxh), pxh);
    }
    u64 rad2 = pk2(rlo, rhi);

    // y = desc[i0] + desc[i1], packed pair of feature lanes
    u64 yv[25];
    const float* p0 = desc + (size_t)i0 * 400 + f2;
    const float* p1 = desc + (size_t)i1 * 400 + f2;
#pragma unroll
    for (int j = 0; j < 25; ++j) {
        u64 a = __ldg(reinterpret_cast<const u64*>(p0 + j * 16));
        u64 b = __ldg(reinterpret_cast<const u64*>(p1 + j * 16));
        yv[j] = add2(a, b);
    }

    float* ob = out + (size_t)e * 800 + f2;
    do_l3<0>(yv, sh, rad2, w, f2, ob);
    do_l3<1>(yv, sh, rad2, w, f2, ob);
    do_l3<2>(yv, sh, rad2, w, f2, ob);
    do_l3<3>(yv, sh, rad2, w, f2, ob);
    do_l3<4>(yv, sh, rad2, w, f2, ob);
}

extern "C" void kernel_launch(void* const* d_in, const int* in_sizes, int n_in,
                              void* d_out, int out_size) {
    const float* desc = (const float*)d_in[0];   // atomic_descriptors
    const float* w    = (const float*)d_in[1];   // tp_weights (33,16)
    const float* disp = (const float*)d_in[2];   // neighbour_displacements (E,3)
    const int*   idx  = (const int*)d_in[3];     // neighbour_indices (E,2)
    int E = in_sizes[3] / 2;
    int total = E * 8;                           // one thread per (edge, feature-pair)
    int block = 128;
    int grid = (total + block - 1) / block;
    bctm_kernel<<<grid, block>>>(desc, w, disp, idx, (float*)d_out, E);
    (void)n_in; (void)out_size;
}

// round 10
// speedup vs baseline: 1.2149x; 1.2149x over previous
#include <cuda_runtime.h>
#include <cstdint>
#include <utility>

#define HD __host__ __device__

using u64 = unsigned long long;

// ---------------------------------------------------------------------------
// Compile-time Clebsch-Gordan machinery (mirrors the numpy reference exactly)
// ---------------------------------------------------------------------------

HD constexpr double cfac(int n) {
    double r = 1.0;
    for (int i = 2; i <= n; ++i) r *= (double)i;
    return r;
}

HD constexpr double csqrt(double x) {
    if (x <= 0.0) return 0.0;
    double g = x > 1.0 ? x : 1.0;
    for (int i = 0; i < 64; ++i) g = 0.5 * (g + x / g);
    return g;
}

HD constexpr int imax3(int a, int b, int c) { int m = a; if (b > m) m = b; if (c > m) m = c; return m; }
HD constexpr int imin3(int a, int b, int c) { int m = a; if (b < m) m = b; if (c < m) m = c; return m; }
HD constexpr int iabs(int a) { return a < 0 ? -a : a; }
HD constexpr double m1p(int k) { return (k & 1) ? -1.0 : 1.0; }

HD constexpr double wcg(int j1, int m1, int j2, int m2, int j3, int m3) {
    if (m1 + m2 != m3) return 0.0;
    if (j3 < iabs(j1 - j2) || j3 > j1 + j2) return 0.0;
    double pre = csqrt((2 * j3 + 1) * cfac(j3 + j1 - j2) * cfac(j3 - j1 + j2) *
                       cfac(j1 + j2 - j3) / cfac(j1 + j2 + j3 + 1));
    pre = pre * csqrt(cfac(j3 + m3) * cfac(j3 - m3) * cfac(j1 - m1) *
                      cfac(j1 + m1) * cfac(j2 - m2) * cfac(j2 + m2));
    double s = 0.0;
    int k0 = imax3(0, j2 - j3 - m1, j1 - j3 + m2);
    int k1 = imin3(j1 + j2 - j3, j1 - m1, j2 + m2);
    for (int k = k0; k <= k1; ++k) {
        s += m1p(k) / (cfac(k) * cfac(j1 + j2 - j3 - k) * cfac(j1 - m1 - k) *
                       cfac(j2 + m2 - k) * cfac(j3 - j2 + m1 + k) * cfac(j3 - j1 - m2 + k));
    }
    return pre * s;
}

struct C2 { double re, im; };
constexpr double S2C = 0.70710678118654752440;

HD constexpr C2 uent(int l, int a, int A) {
    int m = a - l, M = A - l;
    if (m > 0) {
        if (M == m)  return C2{ m1p(m) * S2C, 0.0 };
        if (M == -m) return C2{ S2C, 0.0 };
    } else if (m == 0) {
        if (M == 0) return C2{ 1.0, 0.0 };
    } else {
        int am = -m;
        if (M == m)  return C2{ 0.0, S2C };
        if (M == am) return C2{ 0.0, -m1p(am) * S2C };
    }
    return C2{ 0.0, 0.0 };
}

HD constexpr double rcg_d(int l1, int l2, int l3, int a, int b, int c) {
    double re = 0.0, im = 0.0;
    for (int A = 0; A < 2 * l1 + 1; ++A) {
        for (int B = 0; B < 2 * l2 + 1; ++B) {
            int m1 = A - l1, m2 = B - l2, m3 = m1 + m2;
            if (m3 < -l3 || m3 > l3) continue;
            double cgv = wcg(l1, m1, l2, m2, l3, m3);
            if (cgv == 0.0) continue;
            C2 u1 = uent(l1, a, A);
            if (u1.re == 0.0 && u1.im == 0.0) continue;
            C2 u2 = uent(l2, b, B);
            if (u2.re == 0.0 && u2.im == 0.0) continue;
            C2 u3 = uent(l3, c, m3 + l3);
            double pr = u1.re * u2.re - u1.im * u2.im;
            double pi = u1.re * u2.im + u1.im * u2.re;
            re += (pr * u3.re + pi * u3.im) * cgv;
            im += (pi * u3.re - pr * u3.im) * cgv;
        }
    }
    return ((l1 + l2 + l3) & 1) ? im : re;
}

HD constexpr float rcg_f(int l1, int l2, int l3, int a, int b, int c) {
    double v = rcg_d(l1, l2, l3, a, b, c);
    return (v > 1e-8 || v < -1e-8) ? (float)v : 0.0f;
}

// nnz across the c-row for (a,b)
HD constexpr int nnz_ab(int l1, int l2, int l3, int a, int b) {
    int k = 0;
    for (int c = 0; c < 2 * l3 + 1; ++c)
        if (rcg_f(l1, l2, l3, a, b, c) != 0.0f) ++k;
    return k;
}
// true if the row's single nonzero equals exactly 1.0f
HD constexpr bool identity_ab(int l1, int l2, int l3, int a, int b) {
    if (nnz_ab(l1, l2, l3, a, b) != 1) return false;
    for (int c = 0; c < 2 * l3 + 1; ++c) {
        float g = rcg_f(l1, l2, l3, a, b, c);
        if (g != 0.0f) return g == 1.0f;
    }
    return false;
}

// ---------------------------------------------------------------------------
// constexpr IEEE754 encode: float -> bits; duplicate into 64-bit (g,g) pair
// ---------------------------------------------------------------------------
HD constexpr unsigned f2b(float x) {
    if (x == 0.0f) return 0u;
    unsigned s = 0; double v = x;
    if (v < 0.0) { s = 0x80000000u; v = -v; }
    int e = 0;
    while (v >= 2.0) { v *= 0.5; ++e; }
    while (v < 1.0)  { v *= 2.0; --e; }
    double mf = (v - 1.0) * 8388608.0;
    unsigned mant = (unsigned)(mf + 0.5);
    if (mant == 8388608u) { mant = 0; ++e; }
    return s | ((unsigned)(e + 127) << 23) | mant;
}
HD constexpr u64 dup2(float x) {
    unsigned b = f2b(x);
    return ((u64)b << 32) | (u64)b;
}

// ---------------------------------------------------------------------------
// Path table
// ---------------------------------------------------------------------------
constexpr int NPATH = 33;
HD constexpr int PL1f(int p) {
    constexpr int t[NPATH] = {0,0,0,0,0, 1,1,1,1,1,1,1,1,1,1,1,1, 2,2,2,2,2,2,2,2,2,2,2,2,2,2,2,2};
    return t[p];
}
HD constexpr int PL2f(int p) {
    constexpr int t[NPATH] = {0,1,2,3,4, 0,1,1,1,2,2,2,3,3,3,4,4, 0,1,1,1,2,2,2,2,2,3,3,3,3,4,4,4};
    return t[p];
}
HD constexpr int PL3f(int p) {
    constexpr int t[NPATH] = {0,1,2,3,4, 1,0,1,2,1,2,3,2,3,4,3,4, 2,1,2,3,0,1,2,3,4,1,2,3,4,2,3,4};
    return t[p];
}

// ---------------------------------------------------------------------------
// static_for
// ---------------------------------------------------------------------------
template <class F, int... Is>
__device__ __forceinline__ void sf_impl(F&& f, std::integer_sequence<int, Is...>) {
    (f(std::integral_constant<int, Is>{}), ...);
}
template <int N, class F>
__device__ __forceinline__ void static_for(F&& f) {
    sf_impl(static_cast<F&&>(f), std::make_integer_sequence<int, N>{});
}

// ---------------------------------------------------------------------------
// packed f32x2 primitives
// ---------------------------------------------------------------------------
__device__ __forceinline__ u64 pk2(float lo, float hi) {
    u64 r; asm("mov.b64 %0, {%1, %2};" : "=l"(r) : "f"(lo), "f"(hi)); return r;
}
__device__ __forceinline__ u64 fma2(u64 a, u64 b, u64 c) {
    u64 d; asm("fma.rn.f32x2 %0, %1, %2, %3;" : "=l"(d) : "l"(a), "l"(b), "l"(c)); return d;
}
__device__ __forceinline__ u64 mul2(u64 a, u64 b) {
    u64 d; asm("mul.rn.f32x2 %0, %1, %2;" : "=l"(d) : "l"(a), "l"(b)); return d;
}
__device__ __forceinline__ u64 add2(u64 a, u64 b) {
    u64 d; asm("add.rn.f32x2 %0, %1, %2;" : "=l"(d) : "l"(a), "l"(b)); return d;
}

// ---------------------------------------------------------------------------
// Kernel: one thread handles one edge x one feature PAIR (f=2fp, 2fp+1)
// ---------------------------------------------------------------------------

template <int L3, int P>
__device__ __forceinline__ void do_path(u64 (&acc)[2][2 * L3 + 1],
                                        const u64 (&yv)[25], const float (&sh)[9],
                                        u64 rad2, const float* __restrict__ w, int f2) {
    constexpr int l1 = PL1f(P);
    constexpr int l2 = PL2f(P);
    constexpr int par = (l1 + l2 + L3) & 1;
    // packed weights for both features of this thread, times radial
    u64 w2 = __ldg(reinterpret_cast<const u64*>(w + P * 16 + f2));
    u64 wr = mul2(w2, rad2);
    static_for<2 * l1 + 1>([&](auto IA) {
        constexpr int a = decltype(IA)::value;
        float shs = sh[l1 * l1 + a];
        u64 pa = mul2(wr, pk2(shs, shs));
        static_for<2 * l2 + 1>([&](auto IB) {
            constexpr int b = decltype(IB)::value;
            constexpr int nnz = nnz_ab(l1, l2, L3, a, b);
            if constexpr (nnz == 1 && identity_ab(l1, l2, L3, a, b)) {
                // G entry is exactly 1 (identity paths): fuse, no prod mul
                static_for<2 * L3 + 1>([&](auto IC) {
                    constexpr int c = decltype(IC)::value;
                    constexpr float g = rcg_f(l1, l2, L3, a, b, c);
                    if constexpr (g != 0.0f) {
                        acc[par][c] = fma2(pa, yv[l2 * l2 + b], acc[par][c]);
                    }
                });
            } else if constexpr (nnz > 0) {
                u64 prod = mul2(pa, yv[l2 * l2 + b]);
                static_for<2 * L3 + 1>([&](auto IC) {
                    constexpr int c = decltype(IC)::value;
                    constexpr float g = rcg_f(l1, l2, L3, a, b, c);
                    if constexpr (g != 0.0f) {
                        constexpr u64 GG = dup2(g);
                        acc[par][c] = fma2(GG, prod, acc[par][c]);
                    }
                });
            }
        });
    });
}

template <int L3>
__device__ __forceinline__ void do_l3(const u64 (&yv)[25], const float (&sh)[9],
                                      u64 rad2, const float* __restrict__ w, int f2,
                                      float* __restrict__ ob) {
    u64 acc[2][2 * L3 + 1];
#pragma unroll
    for (int p = 0; p < 2; ++p)
#pragma unroll
        for (int c = 0; c < 2 * L3 + 1; ++c) acc[p][c] = 0ull;

    static_for<NPATH>([&](auto IP) {
        constexpr int P = decltype(IP)::value;
        if constexpr (PL3f(P) == L3) {
            do_path<L3, P>(acc, yv, sh, rad2, w, f2);
        }
    });

#pragma unroll
    for (int par = 0; par < 2; ++par)
#pragma unroll
        for (int c = 0; c < 2 * L3 + 1; ++c)
            *reinterpret_cast<u64*>(ob + (par * 25 + L3 * L3 + c) * 16) = acc[par][c];
}

__global__ __launch_bounds__(128, 5)
void bctm_kernel(const float* __restrict__ desc,   // (N_ATOMS, 1, 25, 16)
                 const float* __restrict__ w,      // (33, 16)
                 const float* __restrict__ disp,   // (E, 3)
                 const int* __restrict__ idx,      // (E, 2)
                 float* __restrict__ out,          // (E, 2, 25, 16)
                 int E) {
    int t = blockIdx.x * blockDim.x + threadIdx.x;
    int e = t >> 3;
    int fp = t & 7;          // feature pair index: features 2fp, 2fp+1
    int f2 = fp * 2;
    if (e >= E) return;

    int i0 = __ldg(idx + 2 * e);
    int i1 = __ldg(idx + 2 * e + 1);
    float dx = __ldg(disp + 3 * e);
    float dy = __ldg(disp + 3 * e + 1);
    float dz = __ldg(disp + 3 * e + 2);

    float r = sqrtf(dx * dx + dy * dy + dz * dz);
    float inv = 1.0f / fmaxf(r, 1e-9f);
    float ux = dx * inv, uy = dy * inv, uz = dz * inv;

    // spherical harmonics, scalar (identical for both packed feature lanes)
    float sh[9];
    {
        const float c1 = 0.4886025119029199f;
        const float c2 = 1.0925484305920792f;
        sh[0] = 0.28209479177387814f;
        sh[1] = c1 * uy;
        sh[2] = c1 * uz;
        sh[3] = c1 * ux;
        sh[4] = c2 * ux * uy;
        sh[5] = c2 * uy * uz;
        sh[6] = 0.31539156525252005f * (3.0f * uz * uz - 1.0f);
        sh[7] = c2 * ux * uz;
        sh[8] = 0.5f * c2 * (ux * ux - uy * uy);
    }

    // radial sinc for the two features of this thread
    float rlo = 0.0f, rhi = 0.0f;
    if (r < 5.0f) {
        float pxl = 0.6283185307179586f * (float)(f2 + 1) * r;
        float pxh = 0.6283185307179586f * (float)(f2 + 2) * r;
        rlo = (pxl < 1e-6f) ? 1.0f : __fdividef(__sinf(pxl), pxl);
        rhi = (pxh < 1e-6f) ? 1.0f : __fdividef(__sinf(pxh), pxh);
    }
    u64 rad2 = pk2(rlo, rhi);

    // y = desc[i0] + desc[i1], packed pair of feature lanes
    u64 yv[25];
    const float* p0 = desc + (size_t)i0 * 400 + f2;
    const float* p1 = desc + (size_t)i1 * 400 + f2;
#pragma unroll
    for (int j = 0; j < 25; ++j) {
        u64 a = __ldg(reinterpret_cast<const u64*>(p0 + j * 16));
        u64 b = __ldg(reinterpret_cast<const u64*>(p1 + j * 16));
        yv[j] = add2(a, b);
    }

    float* ob = out + (size_t)e * 800 + f2;
    do_l3<0>(yv, sh, rad2, w, f2, ob);
    do_l3<1>(yv, sh, rad2, w, f2, ob);
    do_l3<2>(yv, sh, rad2, w, f2, ob);
    do_l3<3>(yv, sh, rad2, w, f2, ob);
    do_l3<4>(yv, sh, rad2, w, f2, ob);
}

extern "C" void kernel_launch(void* const* d_in, const int* in_sizes, int n_in,
                              void* d_out, int out_size) {
    const float* desc = (const float*)d_in[0];   // atomic_descriptors
    const float* w    = (const float*)d_in[1];   // tp_weights (33,16)
    const float* disp = (const float*)d_in[2];   // neighbour_displacements (E,3)
    const int*   idx  = (const int*)d_in[3];     // neighbour_indices (E,2)
    int E = in_sizes[3] / 2;
    int total = E * 8;                           // one thread per (edge, feature-pair)
    int block = 128;
    int grid = (total + block - 1) / block;
    bctm_kernel<<<grid, block>>>(desc, w, disp, idx, (float*)d_out, E);
    (void)n_in; (void)out_size;
}